// round 9
// baseline (speedup 1.0000x reference)
#include <cuda_runtime.h>

#define NU 100000
#define NJ 100000
#define NN 200000
#define EE 3200000
#define DD 64
#define BB 16384
#define SCAN_BLK 196   // ceil(NN/1024)

// ---------------- static scratch ----------------
__device__ int   g_is64;           // 1 if index inputs are int64, 0 if int32
__device__ int   g_deg[NN];        // in-degree (by col), excludes self loop
__device__ float g_dinv[NN];
__device__ int   g_offs[NN];       // exclusive scan of deg
__device__ int   g_cnt[NN];        // fill cursors
__device__ int   g_bsums[SCAN_BLK];
__device__ int   g_r32[EE];        // int32 edge sources
__device__ int   g_c32[EE];        // int32 edge targets
__device__ int   g_csr_src[EE];    // source row per CSR slot
__device__ __align__(16) float g_h [(size_t)NN * DD];  // prescaled x@W
__device__ __align__(16) float g_x1[(size_t)NN * DD];  // layer output

// ---------------- dtype detection ----------------
// int64 data: odd 32-bit words are zero high-halves. int32 data: odd words are
// random node ids (zero with prob ~1/200000). 32-word vote is decisive.
__global__ void k_detect(const int* __restrict__ w) {
    int t = threadIdx.x;
    int z = (w[2 * t + 1] == 0) ? 1 : 0;
#pragma unroll
    for (int o = 16; o; o >>= 1) z += __shfl_down_sync(0xffffffffu, z, o);
    if (t == 0) g_is64 = (z >= 30) ? 1 : 0;
}

__device__ __forceinline__ int load_idx(const void* p, size_t i) {
    return g_is64 ? (int)((const long long*)p)[i] : ((const int*)p)[i];
}

// ---------------- degree / norm ----------------
__global__ void k_deg_zero() {
    int i = blockIdx.x * 256 + threadIdx.x;
    if (i < NN) g_deg[i] = 0;
}

// index load (either dtype) -> int32 cache + in-degree count
__global__ void k_deg(const void* __restrict__ ei) {
    int e = blockIdx.x * 256 + threadIdx.x;
    if (e < EE) {
        int r = load_idx(ei, e);
        int c = load_idx(ei, (size_t)EE + e);
        g_r32[e] = r;
        g_c32[e] = c;
        atomicAdd(&g_deg[c], 1);
    }
}

__global__ void k_dinv() {
    int i = blockIdx.x * 256 + threadIdx.x;
    if (i < NN) g_dinv[i] = rsqrtf((float)g_deg[i] + 1.0f);  // +1 self loop
}

// ---------------- exclusive scan (3 kernels) ----------------
__global__ void k_scan1() {
    __shared__ int s[256];
    int tid = threadIdx.x;
    int base = blockIdx.x * 1024 + tid * 4;
    int v = 0;
#pragma unroll
    for (int q = 0; q < 4; q++) { int i = base + q; if (i < NN) v += g_deg[i]; }
    s[tid] = v; __syncthreads();
    for (int o = 128; o; o >>= 1) {
        if (tid < o) s[tid] += s[tid + o];
        __syncthreads();
    }
    if (tid == 0) g_bsums[blockIdx.x] = s[0];
}

__global__ void k_scan2() {
    if (threadIdx.x == 0) {
        int acc = 0;
        for (int b = 0; b < SCAN_BLK; b++) { int t = g_bsums[b]; g_bsums[b] = acc; acc += t; }
    }
}

__global__ void k_scan3() {
    __shared__ int s[256];
    int tid = threadIdx.x;
    int base = blockIdx.x * 1024 + tid * 4;
    int d[4]; int v = 0;
#pragma unroll
    for (int q = 0; q < 4; q++) {
        int i = base + q;
        d[q] = (i < NN) ? g_deg[i] : 0;
        v += d[q];
    }
    s[tid] = v; __syncthreads();
    // inclusive Hillis-Steele
    for (int o = 1; o < 256; o <<= 1) {
        int t = (tid >= o) ? s[tid - o] : 0;
        __syncthreads();
        s[tid] += t;
        __syncthreads();
    }
    int off = g_bsums[blockIdx.x] + s[tid] - v;  // exclusive
#pragma unroll
    for (int q = 0; q < 4; q++) {
        int i = base + q;
        if (i < NN) { g_offs[i] = off; g_cnt[i] = 0; off += d[q]; }
    }
}

__global__ void k_fill() {
    int e = blockIdx.x * 256 + threadIdx.x;
    if (e < EE) {
        int r = g_r32[e];
        int c = g_c32[e];
        int slot = g_offs[c] + atomicAdd(&g_cnt[c], 1);
        g_csr_src[slot] = r;
    }
}

// ---------------- GEMM: h = (x @ W) * dinv ----------------
__global__ void __launch_bounds__(256) k_gemm(const float* __restrict__ p0,
                                              const float* __restrict__ p1,
                                              const float* __restrict__ W,
                                              int use_x1) {
    __shared__ __align__(16) float Ws[64 * 64];
    __shared__ float Xs[64 * 65];  // [k][row], pad to kill conflicts
    const int tid  = threadIdx.x;
    const int row0 = blockIdx.x * 64;

#pragma unroll
    for (int i = tid; i < 4096; i += 256) Ws[i] = W[i];
#pragma unroll
    for (int i = tid; i < 4096; i += 256) {
        int r = i >> 6, k = i & 63;
        int row = row0 + r;
        float v;
        if (use_x1) v = g_x1[(size_t)row * 64 + k];
        else        v = (row < NU) ? p0[(size_t)row * 64 + k]
                                   : p1[(size_t)(row - NU) * 64 + k];
        Xs[k * 65 + r] = v;
    }
    __syncthreads();

    const int tx = tid & 15, ty = tid >> 4;
    const int c0 = tx * 4, r0 = ty * 4;
    float acc[4][4] = {};
#pragma unroll
    for (int k = 0; k < 64; k++) {
        float4 wv = *(const float4*)&Ws[k * 64 + c0];
#pragma unroll
        for (int i = 0; i < 4; i++) {
            float xv = Xs[k * 65 + r0 + i];
            acc[i][0] = fmaf(xv, wv.x, acc[i][0]);
            acc[i][1] = fmaf(xv, wv.y, acc[i][1]);
            acc[i][2] = fmaf(xv, wv.z, acc[i][2]);
            acc[i][3] = fmaf(xv, wv.w, acc[i][3]);
        }
    }
#pragma unroll
    for (int i = 0; i < 4; i++) {
        int row = row0 + r0 + i;
        float d = g_dinv[row];
        float4 o = make_float4(acc[i][0] * d, acc[i][1] * d, acc[i][2] * d, acc[i][3] * d);
        *(float4*)&g_h[(size_t)row * 64 + c0] = o;
    }
}

// ---------------- aggregate + epilogue (warp per node) ----------------
// x1[i] = act( dinv[i] * (h[i] + sum_{r in N(i)} h[r]) + bias )
__global__ void __launch_bounds__(256) k_agg(const float* __restrict__ bias, int relu) {
    int g = blockIdx.x * 256 + threadIdx.x;   // grid = NN*32/256 exact
    int node = g >> 5, lane = g & 31;
    const float2* __restrict__ hp = (const float2*)g_h;
    size_t self = (size_t)node * 32 + lane;   // float2 index
    float2 acc = hp[self];                    // self-loop term
    float2 acc1 = make_float2(0.f, 0.f);
    int s = g_offs[node];
    int n = g_deg[node];
    int j = 0;
    for (; j + 4 <= n; j += 4) {
        int r0 = g_csr_src[s + j + 0];
        int r1 = g_csr_src[s + j + 1];
        int r2 = g_csr_src[s + j + 2];
        int r3 = g_csr_src[s + j + 3];
        float2 v0 = hp[(size_t)r0 * 32 + lane];
        float2 v1 = hp[(size_t)r1 * 32 + lane];
        float2 v2 = hp[(size_t)r2 * 32 + lane];
        float2 v3 = hp[(size_t)r3 * 32 + lane];
        acc.x  += v0.x; acc.y  += v0.y;
        acc1.x += v1.x; acc1.y += v1.y;
        acc.x  += v2.x; acc.y  += v2.y;
        acc1.x += v3.x; acc1.y += v3.y;
    }
    for (; j < n; j++) {
        int r = g_csr_src[s + j];
        float2 v = hp[(size_t)r * 32 + lane];
        acc.x += v.x; acc.y += v.y;
    }
    acc.x += acc1.x; acc.y += acc1.y;
    float d = g_dinv[node];
    float2 b2 = ((const float2*)bias)[lane];
    float ox = fmaf(d, acc.x, b2.x);
    float oy = fmaf(d, acc.y, b2.y);
    if (relu) { ox = fmaxf(ox, 0.f); oy = fmaxf(oy, 0.f); }
    ((float2*)g_x1)[self] = make_float2(ox, oy);
}

// ---------------- predictor ----------------
__global__ void __launch_bounds__(256) k_predict(const void* __restrict__ ui,
                                                 const void* __restrict__ ji,
                                                 const float* __restrict__ pw,
                                                 const float* __restrict__ pb,
                                                 float* __restrict__ out) {
    int t = blockIdx.x * 256 + threadIdx.x;   // grid = BB*32/256 exact
    int b = t >> 5, lane = t & 31;
    int u = load_idx(ui, b);
    int j = load_idx(ji, b);
    const float* __restrict__ xu = &g_x1[(size_t)u * 64];
    const float* __restrict__ xj = &g_x1[((size_t)NU + (size_t)j) * 64];
    float a0 = xu[lane];
    float a1 = xu[lane + 32];
    float a2 = xj[lane];
    float a3 = xj[lane + 32];
    float s = a0 * pw[lane] + a1 * pw[lane + 32]
            + a2 * pw[64 + lane] + a3 * pw[96 + lane];
#pragma unroll
    for (int off = 16; off; off >>= 1) s += __shfl_down_sync(0xffffffffu, s, off);
    if (lane == 0) out[b] = s + pb[0];
}

// ---------------------------------------------------------------------------
extern "C" void kernel_launch(void* const* d_in, const int* in_sizes, int n_in,
                              void* d_out, int out_size) {
    const void*  ei = d_in[0];
    const void*  ui = d_in[1];
    const void*  ji = d_in[2];
    const float* uw = (const float*)d_in[3];
    const float* jw = (const float*)d_in[4];
    const float* W1 = (const float*)d_in[5];
    const float* b1 = (const float*)d_in[6];
    const float* W2 = (const float*)d_in[7];
    const float* b2 = (const float*)d_in[8];
    const float* pw = (const float*)d_in[9];
    const float* pb = (const float*)d_in[10];
    float* out = (float*)d_out;

    const int nb_node = (NN + 255) / 256;
    const int nb_edge = (EE + 255) / 256;
    const int nb_agg  = (NN * 32) / 256;   // 25000 exact

    // dtype probe + degree / normalization / CSR (recomputed every call)
    k_detect<<<1, 32>>>((const int*)ei);
    k_deg_zero<<<nb_node, 256>>>();
    k_deg<<<nb_edge, 256>>>(ei);
    k_dinv<<<nb_node, 256>>>();
    k_scan1<<<SCAN_BLK, 256>>>();
    k_scan2<<<1, 32>>>();
    k_scan3<<<SCAN_BLK, 256>>>();
    k_fill<<<nb_edge, 256>>>();

    // layer 1
    k_gemm<<<NN / 64, 256>>>(uw, jw, W1, 0);
    k_agg<<<nb_agg, 256>>>(b1, 1);

    // layer 2
    k_gemm<<<NN / 64, 256>>>(nullptr, nullptr, W2, 1);
    k_agg<<<nb_agg, 256>>>(b2, 0);

    // predictor
    k_predict<<<(BB * 32) / 256, 256>>>(ui, ji, pw, pb, out);
}

// round 12
// speedup vs baseline: 1.2096x; 1.2096x over previous
#include <cuda_runtime.h>

#define NU 100000
#define NJ 100000
#define NN 200000
#define EE 3200000
#define DD 64
#define BB 16384
#define SCAN_BLK 196   // ceil(NN/1024)

// ---------------- static scratch ----------------
__device__ int   g_is64;           // 1 if index inputs are int64, 0 if int32
__device__ int   g_deg[NN];        // in-degree (by col), excludes self loop
__device__ float g_dinv[NN];
__device__ int   g_offs[NN];       // exclusive scan of deg
__device__ int   g_cnt[NN];        // fill cursors
__device__ int   g_bsums[SCAN_BLK];
__device__ int   g_r32[EE];        // int32 edge sources
__device__ int   g_c32[EE];        // int32 edge targets
__device__ int   g_csr_src[EE];    // source row per CSR slot
__device__ __align__(16) float g_h [(size_t)NN * DD];  // prescaled x@W
__device__ __align__(16) float g_x1[(size_t)NN * DD];  // layer-1 output

// Packed f32x2 helpers (Blackwell): 2 FMAs per fma-pipe slot.
#define FMA2(acc, a, b) asm("fma.rn.f32x2 %0, %1, %2, %0;" : "+l"(acc) : "l"(a), "l"(b))
#define PACK2(p, x)     asm("mov.b64 %0, {%1, %1};" : "=l"(p) : "f"(x))
#define UNPACK2(lo, hi, p) asm("mov.b64 {%0, %1}, %2;" : "=f"(lo), "=f"(hi) : "l"(p))

// ---------------- dtype detection ----------------
__global__ void k_detect(const int* __restrict__ w) {
    int t = threadIdx.x;
    int z = (w[2 * t + 1] == 0) ? 1 : 0;
#pragma unroll
    for (int o = 16; o; o >>= 1) z += __shfl_down_sync(0xffffffffu, z, o);
    if (t == 0) g_is64 = (z >= 30) ? 1 : 0;
}

__device__ __forceinline__ int load_idx(const void* p, size_t i) {
    return g_is64 ? (int)((const long long*)p)[i] : ((const int*)p)[i];
}

// ---------------- degree / norm ----------------
__global__ void k_deg_zero() {
    int i = blockIdx.x * 256 + threadIdx.x;
    if (i < NN) g_deg[i] = 0;
}

__global__ void k_deg(const void* __restrict__ ei) {
    int e = blockIdx.x * 256 + threadIdx.x;
    if (e < EE) {
        int r = load_idx(ei, e);
        int c = load_idx(ei, (size_t)EE + e);
        g_r32[e] = r;
        g_c32[e] = c;
        atomicAdd(&g_deg[c], 1);
    }
}

__global__ void k_dinv() {
    int i = blockIdx.x * 256 + threadIdx.x;
    if (i < NN) g_dinv[i] = rsqrtf((float)g_deg[i] + 1.0f);  // +1 self loop
}

// ---------------- exclusive scan (3 kernels) ----------------
__global__ void k_scan1() {
    __shared__ int s[256];
    int tid = threadIdx.x;
    int base = blockIdx.x * 1024 + tid * 4;
    int v = 0;
#pragma unroll
    for (int q = 0; q < 4; q++) { int i = base + q; if (i < NN) v += g_deg[i]; }
    s[tid] = v; __syncthreads();
    for (int o = 128; o; o >>= 1) {
        if (tid < o) s[tid] += s[tid + o];
        __syncthreads();
    }
    if (tid == 0) g_bsums[blockIdx.x] = s[0];
}

__global__ void k_scan2() {
    if (threadIdx.x == 0) {
        int acc = 0;
        for (int b = 0; b < SCAN_BLK; b++) { int t = g_bsums[b]; g_bsums[b] = acc; acc += t; }
    }
}

__global__ void k_scan3() {
    __shared__ int s[256];
    int tid = threadIdx.x;
    int base = blockIdx.x * 1024 + tid * 4;
    int d[4]; int v = 0;
#pragma unroll
    for (int q = 0; q < 4; q++) {
        int i = base + q;
        d[q] = (i < NN) ? g_deg[i] : 0;
        v += d[q];
    }
    s[tid] = v; __syncthreads();
    for (int o = 1; o < 256; o <<= 1) {
        int t = (tid >= o) ? s[tid - o] : 0;
        __syncthreads();
        s[tid] += t;
        __syncthreads();
    }
    int off = g_bsums[blockIdx.x] + s[tid] - v;  // exclusive
#pragma unroll
    for (int q = 0; q < 4; q++) {
        int i = base + q;
        if (i < NN) { g_offs[i] = off; g_cnt[i] = 0; off += d[q]; }
    }
}

__global__ void k_fill() {
    int e = blockIdx.x * 256 + threadIdx.x;
    if (e < EE) {
        int r = g_r32[e];
        int c = g_c32[e];
        int slot = g_offs[c] + atomicAdd(&g_cnt[c], 1);
        g_csr_src[slot] = r;
    }
}

// ---------------- GEMM: h = (x @ W) * dinv  (f32x2 packed FMA) ----------------
__global__ void __launch_bounds__(256) k_gemm(const float* __restrict__ p0,
                                              const float* __restrict__ p1,
                                              const float* __restrict__ W,
                                              int use_x1) {
    __shared__ __align__(16) float Ws[64 * 64];
    __shared__ float Xs[64 * 65];
    const int tid  = threadIdx.x;
    const int row0 = blockIdx.x * 64;

#pragma unroll
    for (int i = tid; i < 4096; i += 256) Ws[i] = W[i];
#pragma unroll
    for (int i = tid; i < 4096; i += 256) {
        int r = i >> 6, k = i & 63;
        int row = row0 + r;
        float v;
        if (use_x1) v = g_x1[(size_t)row * 64 + k];
        else        v = (row < NU) ? p0[(size_t)row * 64 + k]
                                   : p1[(size_t)(row - NU) * 64 + k];
        Xs[k * 65 + r] = v;
    }
    __syncthreads();

    const int tx = tid & 15, ty = tid >> 4;
    const int c0 = tx * 4, r0 = ty * 4;
    unsigned long long acc0[4] = {0, 0, 0, 0};  // cols c0, c0+1
    unsigned long long acc1[4] = {0, 0, 0, 0};  // cols c0+2, c0+3
#pragma unroll
    for (int k = 0; k < 64; k++) {
        ulonglong2 wv = *(const ulonglong2*)&Ws[k * 64 + c0];
#pragma unroll
        for (int i = 0; i < 4; i++) {
            float xv = Xs[k * 65 + r0 + i];
            unsigned long long xx;
            PACK2(xx, xv);
            FMA2(acc0[i], xx, wv.x);
            FMA2(acc1[i], xx, wv.y);
        }
    }
#pragma unroll
    for (int i = 0; i < 4; i++) {
        int row = row0 + r0 + i;
        float d = g_dinv[row];
        float a, b, c, e;
        UNPACK2(a, b, acc0[i]);
        UNPACK2(c, e, acc1[i]);
        float4 o = make_float4(a * d, b * d, c * d, e * d);
        *(float4*)&g_h[(size_t)row * 64 + c0] = o;
    }
}

// ---------------- shared aggregation core (float2 per lane) ----------------
__device__ __forceinline__ float2 agg_node(int node, int lane,
                                           const float2* __restrict__ hp) {
    size_t self = (size_t)node * 32 + lane;
    float2 acc = hp[self];                    // self-loop term
    float2 acc1 = make_float2(0.f, 0.f);
    int s = g_offs[node];
    int n = g_deg[node];
    int j = 0;
    for (; j + 4 <= n; j += 4) {
        int r0 = g_csr_src[s + j + 0];
        int r1 = g_csr_src[s + j + 1];
        int r2 = g_csr_src[s + j + 2];
        int r3 = g_csr_src[s + j + 3];
        float2 v0 = hp[(size_t)r0 * 32 + lane];
        float2 v1 = hp[(size_t)r1 * 32 + lane];
        float2 v2 = hp[(size_t)r2 * 32 + lane];
        float2 v3 = hp[(size_t)r3 * 32 + lane];
        acc.x  += v0.x; acc.y  += v0.y;
        acc1.x += v1.x; acc1.y += v1.y;
        acc.x  += v2.x; acc.y  += v2.y;
        acc1.x += v3.x; acc1.y += v3.y;
    }
    for (; j < n; j++) {
        int r = g_csr_src[s + j];
        float2 v = hp[(size_t)r * 32 + lane];
        acc.x += v.x; acc.y += v.y;
    }
    acc.x += acc1.x; acc.y += acc1.y;
    return acc;
}

// ---------------- layer-1 aggregate + epilogue (warp per node, all nodes) ----
__global__ void __launch_bounds__(256) k_agg1(const float* __restrict__ bias) {
    int g = blockIdx.x * 256 + threadIdx.x;   // grid = NN*32/256 exact
    int node = g >> 5, lane = g & 31;
    float2 acc = agg_node(node, lane, (const float2*)g_h);
    float d = g_dinv[node];
    float2 b2 = ((const float2*)bias)[lane];
    float ox = fmaxf(fmaf(d, acc.x, b2.x), 0.f);   // ReLU
    float oy = fmaxf(fmaf(d, acc.y, b2.y), 0.f);
    ((float2*)g_x1)[(size_t)node * 32 + lane] = make_float2(ox, oy);
}

// ---------------- fused layer-2 aggregate + predictor (warp per batch elem) --
// Only aggregates the ~32K batch node instances instead of all 200K nodes.
__global__ void __launch_bounds__(256) k_agg2_predict(const void* __restrict__ ui,
                                                      const void* __restrict__ ji,
                                                      const float* __restrict__ b2v,
                                                      const float* __restrict__ pw,
                                                      const float* __restrict__ pb,
                                                      float* __restrict__ out) {
    int t = blockIdx.x * 256 + threadIdx.x;   // grid = BB*32/256 exact
    int b = t >> 5, lane = t & 31;
    int u  = load_idx(ui, b);
    int jn = NU + load_idx(ji, b);
    const float2* hp = (const float2*)g_h;
    float2 bb = ((const float2*)b2v)[lane];

    float2 au = agg_node(u, lane, hp);
    float du = g_dinv[u];
    float xux = fmaf(du, au.x, bb.x);
    float xuy = fmaf(du, au.y, bb.y);

    float2 aj = agg_node(jn, lane, hp);
    float dj = g_dinv[jn];
    float xjx = fmaf(dj, aj.x, bb.x);
    float xjy = fmaf(dj, aj.y, bb.y);

    float2 pwu = ((const float2*)pw)[lane];        // dims [2l, 2l+1]
    float2 pwj = ((const float2*)pw)[32 + lane];   // dims [64+2l, 64+2l+1]
    float s = xux * pwu.x + xuy * pwu.y + xjx * pwj.x + xjy * pwj.y;
#pragma unroll
    for (int off = 16; off; off >>= 1) s += __shfl_down_sync(0xffffffffu, s, off);
    if (lane == 0) out[b] = s + pb[0];
}

// ---------------------------------------------------------------------------
extern "C" void kernel_launch(void* const* d_in, const int* in_sizes, int n_in,
                              void* d_out, int out_size) {
    const void*  ei = d_in[0];
    const void*  ui = d_in[1];
    const void*  ji = d_in[2];
    const float* uw = (const float*)d_in[3];
    const float* jw = (const float*)d_in[4];
    const float* W1 = (const float*)d_in[5];
    const float* b1 = (const float*)d_in[6];
    const float* W2 = (const float*)d_in[7];
    const float* b2 = (const float*)d_in[8];
    const float* pw = (const float*)d_in[9];
    const float* pb = (const float*)d_in[10];
    float* out = (float*)d_out;

    const int nb_node = (NN + 255) / 256;
    const int nb_edge = (EE + 255) / 256;
    const int nb_agg  = (NN * 32) / 256;   // 25000 exact

    // dtype probe + degree / normalization / CSR (recomputed every call)
    k_detect<<<1, 32>>>((const int*)ei);
    k_deg_zero<<<nb_node, 256>>>();
    k_deg<<<nb_edge, 256>>>(ei);
    k_dinv<<<nb_node, 256>>>();
    k_scan1<<<SCAN_BLK, 256>>>();
    k_scan2<<<1, 32>>>();
    k_scan3<<<SCAN_BLK, 256>>>();
    k_fill<<<nb_edge, 256>>>();

    // layer 1: dense GEMM + dense aggregate
    k_gemm<<<NN / 64, 256>>>(uw, jw, W1, 0);
    k_agg1<<<nb_agg, 256>>>(b1);

    // layer 2: dense GEMM, then aggregate ONLY the batch nodes fused w/ predict
    k_gemm<<<NN / 64, 256>>>(nullptr, nullptr, W2, 1);
    k_agg2_predict<<<(BB * 32) / 256, 256>>>(ui, ji, b2, pw, pb, out);
}